// round 9
// baseline (speedup 1.0000x reference)
#include <cuda_runtime.h>
#include <cstdint>
#include <cstddef>
#include <climits>

#define NPTS     8192
#define BATCH    8
#define MSEL     4096        // ceil(0.5 * 8192)
#define NTHREADS 1024
#define HALF     4096        // points per CTA (cluster of 2 per batch)
#define PPT      4           // points per thread (HALF / NTHREADS)
#define NPAIR    2           // f32x2 pairs per thread

// smem floats: full packed pos pairs [NPTS*6] + warp max [2*32] + warp idx [2*32]
//            + idx list [MSEL] + exch slots [2 u64] + mbars [2 u64]
#define SMEM_FLOATS (NPTS * 6 + 64 + 64 + MSEL + 8)
#define SMEM_BYTES  (SMEM_FLOATS * 4)

__device__ int g_sel_idx[BATCH * MSEL];

// ---------------- f32x2 packed helpers (sm_100+) ----------------
__device__ __forceinline__ unsigned long long pack2(float lo, float hi) {
    unsigned long long r;
    asm("mov.b64 %0, {%1, %2};" : "=l"(r) : "f"(lo), "f"(hi));
    return r;
}
__device__ __forceinline__ void unpack2(unsigned long long v, float& lo, float& hi) {
    asm("mov.b64 {%0, %1}, %2;" : "=f"(lo), "=f"(hi) : "l"(v));
}
__device__ __forceinline__ unsigned long long add2(unsigned long long a, unsigned long long b) {
    unsigned long long r;
    asm("add.rn.f32x2 %0, %1, %2;" : "=l"(r) : "l"(a), "l"(b));
    return r;
}
__device__ __forceinline__ unsigned long long mul2(unsigned long long a, unsigned long long b) {
    unsigned long long r;
    asm("mul.rn.f32x2 %0, %1, %2;" : "=l"(r) : "l"(a), "l"(b));
    return r;
}

// ---------------- cluster / mbarrier helpers ----------------
__device__ __forceinline__ uint32_t smem_u32(const void* p) {
    uint32_t a;
    asm("{ .reg .u64 t; cvta.to.shared.u64 t, %1; cvt.u32.u64 %0, t; }"
        : "=r"(a) : "l"(p));
    return a;
}
__device__ __forceinline__ uint32_t ctarank() {
    uint32_t r;
    asm("mov.u32 %0, %%cluster_ctarank;" : "=r"(r));
    return r;
}
__device__ __forceinline__ uint32_t mapa_peer(uint32_t addr, uint32_t rank) {
    uint32_t r;
    asm("mapa.shared::cluster.u32 %0, %1, %2;" : "=r"(r) : "r"(addr), "r"(rank));
    return r;
}
__device__ __forceinline__ void st_cluster_u64(uint32_t addr, unsigned long long v) {
    asm volatile("st.shared::cluster.u64 [%0], %1;" :: "r"(addr), "l"(v) : "memory");
}
__device__ __forceinline__ void mbar_init(uint32_t addr, uint32_t cnt) {
    asm volatile("mbarrier.init.shared.b64 [%0], %1;" :: "r"(addr), "r"(cnt) : "memory");
}
__device__ __forceinline__ void mbar_arrive_cluster(uint32_t addr) {
    asm volatile("mbarrier.arrive.release.cluster.shared::cluster.b64 _, [%0];"
                 :: "r"(addr) : "memory");
}
__device__ __forceinline__ void mbar_wait(uint32_t addr, uint32_t parity) {
    asm volatile(
        "{\n\t.reg .pred P;\n\t"
        "LW_%=:\n\t"
        "mbarrier.try_wait.parity.acquire.cluster.shared::cta.b64 P, [%0], %1, 0x989680;\n\t"
        "@P bra.uni LD_%=;\n\t"
        "bra.uni LW_%=;\n\t"
        "LD_%=:\n\t}"
        :: "r"(addr), "r"(parity) : "memory");
}
__device__ __forceinline__ void cluster_sync() {
    asm volatile("barrier.cluster.arrive.aligned;" ::: "memory");
    asm volatile("barrier.cluster.wait.aligned;" ::: "memory");
}

extern __shared__ float smem[];

// ---------------- FPS kernel: 2-CTA cluster per batch ----------------
__global__ __launch_bounds__(NTHREADS, 1) __cluster_dims__(2, 1, 1)
void fps_kernel(const float* __restrict__ points, float* __restrict__ dp_out)
{
    float*              s_pos2 = smem;                          // [NPTS*6] {x,x}{y,y}{z,z}
    unsigned*           s_wmax = (unsigned*)(smem + NPTS * 6);  // [2][32]
    int*                s_widx = (int*)(smem + NPTS * 6 + 64);  // [2][32]
    int*                s_idx  = (int*)(smem + NPTS * 6 + 128); // [MSEL]
    unsigned long long* s_ex   = (unsigned long long*)(smem + NPTS * 6 + 128 + MSEL); // [2]
    unsigned long long* s_mb   = s_ex + 2;                      // [2] mbarriers

    const int b    = blockIdx.x >> 1;
    const int rank = (int)ctarank();      // 0 or 1
    const int peer = rank ^ 1;
    const int tid  = threadIdx.x;
    const int lane = tid & 31;
    const int warp = tid >> 5;
    const float* p = points + (size_t)b * NPTS * 3;

    const uint32_t ex_a = smem_u32(s_ex);
    const uint32_t mb_a = smem_u32(s_mb);

    // Stage FULL duplicated point-pair table (both CTAs keep all 8192 points).
    for (int k = tid; k < NPTS * 3; k += NTHREADS) {
        float v = p[k];
        int   i = k / 3, c = k - 3 * i;
        s_pos2[6 * i + 2 * c]     = v;
        s_pos2[6 * i + 2 * c + 1] = v;
    }
    if (tid == 0) {
        mbar_init(mb_a + 0, 1);
        mbar_init(mb_a + 8, 1);
        s_idx[0] = 0;
    }
    __syncthreads();
    cluster_sync();   // mbar inits + pos tables visible cluster-wide

    // Register-resident NEGATED coords of OWN half.
    // pair j: local ids (2j)*1024+tid (lo), (2j+1)*1024+tid (hi); abs = rank*HALF + local.
    unsigned long long NX[NPAIR], NY[NPAIR], NZ[NPAIR];
    float mind[PPT];
#pragma unroll
    for (int i = 0; i < PPT; i++) mind[i] = 1e10f;
#pragma unroll
    for (int j = 0; j < NPAIR; j++) {
        int a0 = rank * HALF + (2 * j) * NTHREADS + tid;
        int a1 = rank * HALF + (2 * j + 1) * NTHREADS + tid;
        NX[j] = pack2(-s_pos2[6 * a0 + 0], -s_pos2[6 * a1 + 0]);
        NY[j] = pack2(-s_pos2[6 * a0 + 2], -s_pos2[6 * a1 + 2]);
        NZ[j] = pack2(-s_pos2[6 * a0 + 4], -s_pos2[6 * a1 + 4]);
    }

    int gidx = 0;            // step 0: index 0 (lives in rank 0's half; table is full)
    int buf  = 0;
    unsigned ph0 = 0, ph1 = 0;  // per-slot mbar phase parity

    for (int step = 1; step < MSEL; ++step) {
        // Broadcast the selected point as pre-duplicated 64-bit pairs (3x LDS.64).
        const unsigned long long* lp = (const unsigned long long*)(s_pos2 + 6 * gidx);
        unsigned long long lx2 = lp[0];
        unsigned long long ly2 = lp[1];
        unsigned long long lz2 = lp[2];

        // XLA-exact: (-x + lx)^2 == (x - lx)^2 bit-exactly; every op rounded, no FMA.
#pragma unroll
        for (int j = 0; j < NPAIR; j++) {
            unsigned long long dx = add2(NX[j], lx2);
            unsigned long long dy = add2(NY[j], ly2);
            unsigned long long dz = add2(NZ[j], lz2);
            unsigned long long sx = mul2(dx, dx);
            unsigned long long sy = mul2(dy, dy);
            unsigned long long sz = mul2(dz, dz);
            unsigned long long dd = add2(add2(sx, sy), sz);
            float d0, d1;
            unpack2(dd, d0, d1);
            mind[2 * j]     = fminf(mind[2 * j], d0);
            mind[2 * j + 1] = fminf(mind[2 * j + 1], d1);
        }
        float vmax = fmaxf(fmaxf(mind[0], mind[1]), fmaxf(mind[2], mind[3]));

        // Stage A: warp max value + lowest tied ABS index within warp.
        unsigned vb   = __float_as_uint(vmax);
        unsigned wmax = __reduce_max_sync(0xffffffffu, vb);
        int cand = INT_MAX;
        if (vb == wmax) {
#pragma unroll
            for (int i = PPT - 1; i >= 0; i--)
                if (__float_as_uint(mind[i]) == vb)
                    cand = rank * HALF + i * NTHREADS + tid;
        }
        int wmin_idx = __reduce_min_sync(0xffffffffu, cand);
        if (lane == 0) {
            s_wmax[buf * 32 + warp] = wmax;
            s_widx[buf * 32 + warp] = wmin_idx;
        }
        __syncthreads();  // single intra-CTA barrier per iteration

        // Stage B: every warp redundantly reduces the 32 warp results -> CTA best.
        unsigned wv   = s_wmax[buf * 32 + lane];
        unsigned cmax = __reduce_max_sync(0xffffffffu, wv);
        int c2   = (wv == cmax) ? s_widx[buf * 32 + lane] : INT_MAX;
        int lidx = __reduce_min_sync(0xffffffffu, c2);

        // Cross-CTA exchange: u64 = (valbits<<32) | ~absidx  (max => val-max, low-idx tie).
        unsigned long long my64 =
            ((unsigned long long)cmax << 32) | (unsigned)(~(unsigned)lidx);
        const int      slot = step & 1;
        const uint32_t off  = (uint32_t)(slot << 3);
        if (tid == 0) {
            st_cluster_u64(mapa_peer(ex_a + off, peer), my64);
            mbar_arrive_cluster(mapa_peer(mb_a + off, peer));
        }
        unsigned par = slot ? ph1 : ph0;
        mbar_wait(mb_a + off, par);
        if (slot) ph1 ^= 1; else ph0 ^= 1;

        unsigned long long tot = my64 > s_ex[slot] ? my64 : s_ex[slot];
        gidx = (int)(~(unsigned)tot);

        if (tid == 0) s_idx[step] = gidx;
        buf ^= 1;
    }
    __syncthreads();
    cluster_sync();   // keep DSMEM alive until both CTAs finish the loop

    // Rank 0 writes outputs for the batch (has full table + full idx list).
    if (rank == 0) {
        for (int r = tid; r < MSEL; r += NTHREADS) {
            int id = s_idx[r];
            g_sel_idx[b * MSEL + r] = id;
            size_t o = ((size_t)b * MSEL + r) * 3;
            dp_out[o + 0] = s_pos2[6 * id + 0];
            dp_out[o + 1] = s_pos2[6 * id + 2];
            dp_out[o + 2] = s_pos2[6 * id + 4];
        }
    }
}

// ---------------- Feature gather: [B, m, 256] float32 ----------------
__global__ void gather_kernel(const float* __restrict__ feat, float* __restrict__ df_out)
{
    int r = blockIdx.x * 4 + (threadIdx.x >> 6);
    int c = threadIdx.x & 63;
    int b = r >> 12;
    int id = g_sel_idx[r];
    const float4* src = (const float4*)(feat + ((size_t)b * NPTS + id) * 256);
    float4 v = src[c];
    ((float4*)df_out)[(size_t)r * 64 + c] = v;
}

extern "C" void kernel_launch(void* const* d_in, const int* in_sizes, int n_in,
                              void* d_out, int out_size)
{
    (void)n_in; (void)out_size;
    const float* points;
    const float* feats;
    if (in_sizes[0] == BATCH * NPTS * 3) {
        points = (const float*)d_in[0];
        feats  = (const float*)d_in[1];
    } else {
        points = (const float*)d_in[1];
        feats  = (const float*)d_in[0];
    }

    float* out = (float*)d_out;
    float* dp  = out;                              // [B, m, 3]
    float* df  = out + (size_t)BATCH * MSEL * 3;   // [B, m, 256]

    cudaFuncSetAttribute(fps_kernel, cudaFuncAttributeMaxDynamicSharedMemorySize,
                         SMEM_BYTES);
    fps_kernel<<<BATCH * 2, NTHREADS, SMEM_BYTES>>>(points, dp);
    gather_kernel<<<(BATCH * MSEL) / 4, 256>>>(feats, df);
}

// round 10
// speedup vs baseline: 2.1004x; 2.1004x over previous
#include <cuda_runtime.h>
#include <cstdint>
#include <cstddef>
#include <climits>

#define NPTS     8192
#define BATCH    8
#define MSEL     4096        // ceil(0.5 * 8192)
#define NTHREADS 512
#define PPT      16          // points per thread
#define NPAIR    8           // f32x2 pairs per thread
// smem floats: packed pos pairs [NPTS*6] + warp max [2*16] + warp idx [2*16] + idx list [MSEL]
#define SMEM_FLOATS (NPTS * 6 + 32 + 32 + MSEL)
#define SMEM_BYTES  (SMEM_FLOATS * 4)

// Selected indices, produced by FPS kernel, consumed by gather kernel.
__device__ int g_sel_idx[BATCH * MSEL];

// ---------------- f32x2 packed helpers (sm_100+) ----------------
__device__ __forceinline__ unsigned long long pack2(float lo, float hi) {
    unsigned long long r;
    asm("mov.b64 %0, {%1, %2};" : "=l"(r) : "f"(lo), "f"(hi));
    return r;
}
__device__ __forceinline__ void unpack2(unsigned long long v, float& lo, float& hi) {
    asm("mov.b64 {%0, %1}, %2;" : "=f"(lo), "=f"(hi) : "l"(v));
}
__device__ __forceinline__ unsigned long long add2(unsigned long long a, unsigned long long b) {
    unsigned long long r;
    asm("add.rn.f32x2 %0, %1, %2;" : "=l"(r) : "l"(a), "l"(b));
    return r;
}
__device__ __forceinline__ unsigned long long mul2(unsigned long long a, unsigned long long b) {
    unsigned long long r;
    asm("mul.rn.f32x2 %0, %1, %2;" : "=l"(r) : "l"(a), "l"(b));
    return r;
}

extern __shared__ float smem[];

// ---------------- FPS kernel: one CTA (512 thr) per batch ----------------
__global__ __launch_bounds__(NTHREADS, 1)
void fps_kernel(const float* __restrict__ points, float* __restrict__ dp_out)
{
    float*    s_pos2 = smem;                          // [NPTS*6] {x,x}{y,y}{z,z} per point
    unsigned* s_wmax = (unsigned*)(smem + NPTS * 6);  // [2][16] per-warp max bits
    int*      s_widx = (int*)(smem + NPTS * 6 + 32);  // [2][16] per-warp min cand idx
    int*      s_idx  = (int*)(smem + NPTS * 6 + 64);  // [MSEL] selected indices

    const int b    = blockIdx.x;
    const int tid  = threadIdx.x;
    const int lane = tid & 31;
    const int warp = tid >> 5;                        // 0..15
    const float* p = points + (size_t)b * NPTS * 3;

    // Stage duplicated point pairs to shared (coalesced gmem reads).
    for (int k = tid; k < NPTS * 3; k += NTHREADS) {
        float v = p[k];
        int   i = k / 3, c = k - 3 * i;
        s_pos2[6 * i + 2 * c]     = v;
        s_pos2[6 * i + 2 * c + 1] = v;
    }
    if (tid == 0) s_idx[0] = 0;
    __syncthreads();

    // Register-resident NEGATED coords: pair j holds ids (2j)*512+tid (lo), (2j+1)*512+tid (hi).
    unsigned long long NX[NPAIR], NY[NPAIR], NZ[NPAIR];
    float mind[PPT];
#pragma unroll
    for (int i = 0; i < PPT; i++) mind[i] = 1e10f;
#pragma unroll
    for (int j = 0; j < NPAIR; j++) {
        int i0 = (2 * j) * NTHREADS + tid;
        int i1 = (2 * j + 1) * NTHREADS + tid;
        NX[j] = pack2(-s_pos2[6 * i0 + 0], -s_pos2[6 * i1 + 0]);
        NY[j] = pack2(-s_pos2[6 * i0 + 2], -s_pos2[6 * i1 + 2]);
        NZ[j] = pack2(-s_pos2[6 * i0 + 4], -s_pos2[6 * i1 + 4]);
    }

    int gidx = 0;  // step 0: deterministic start at index 0
    int buf  = 0;

    for (int step = 1; step < MSEL; ++step) {
        // Broadcast the selected point as pre-duplicated 64-bit pairs (3x LDS.64).
        const unsigned long long* lp =
            (const unsigned long long*)(s_pos2 + 6 * gidx);
        unsigned long long lx2 = lp[0];
        unsigned long long ly2 = lp[1];
        unsigned long long lz2 = lp[2];

        // XLA-exact: (-x + lx)^2 == (x - lx)^2 bit-exactly; every op rounded, no FMA.
#pragma unroll
        for (int j = 0; j < NPAIR; j++) {
            unsigned long long dx = add2(NX[j], lx2);
            unsigned long long dy = add2(NY[j], ly2);
            unsigned long long dz = add2(NZ[j], lz2);
            unsigned long long sx = mul2(dx, dx);
            unsigned long long sy = mul2(dy, dy);
            unsigned long long sz = mul2(dz, dz);
            unsigned long long dd = add2(add2(sx, sy), sz);
            float d0, d1;
            unpack2(dd, d0, d1);
            mind[2 * j]     = fminf(mind[2 * j], d0);
            mind[2 * j + 1] = fminf(mind[2 * j + 1], d1);
        }

        // Max-tree over the 16 running minima (depth 4).
        float t0 = fmaxf(fmaxf(mind[0],  mind[1]),  fmaxf(mind[2],  mind[3]));
        float t1 = fmaxf(fmaxf(mind[4],  mind[5]),  fmaxf(mind[6],  mind[7]));
        float t2 = fmaxf(fmaxf(mind[8],  mind[9]),  fmaxf(mind[10], mind[11]));
        float t3 = fmaxf(fmaxf(mind[12], mind[13]), fmaxf(mind[14], mind[15]));
        float vmax = fmaxf(fmaxf(t0, t1), fmaxf(t2, t3));

        // Stage A: warp max value + lowest tied index within warp (search overlaps REDUX).
        unsigned vb   = __float_as_uint(vmax);  // nonneg floats: uint order == float order
        unsigned wmax = __reduce_max_sync(0xffffffffu, vb);
        int cand = INT_MAX;
        if (vb == wmax) {
            // high-to-low so the LOWEST tied index wins last.
#pragma unroll
            for (int i = PPT - 1; i >= 0; i--)
                if (__float_as_uint(mind[i]) == vb) cand = i * NTHREADS + tid;
        }
        int wmin_idx = __reduce_min_sync(0xffffffffu, cand);
        if (lane == 0) {
            s_wmax[buf * 16 + warp] = wmax;
            s_widx[buf * 16 + warp] = wmin_idx;
        }
        __syncthreads();  // single barrier per iteration

        // Stage B: every warp redundantly reduces across the 16 warp results.
        // Lanes 16..31 mirror lanes 0..15 (same data) — harmless for max/min.
        unsigned wv   = s_wmax[buf * 16 + (lane & 15)];
        unsigned gmax = __reduce_max_sync(0xffffffffu, wv);
        int c2 = (wv == gmax) ? s_widx[buf * 16 + (lane & 15)] : INT_MAX;
        gidx   = __reduce_min_sync(0xffffffffu, c2);

        if (tid == 0) s_idx[step] = gidx;   // 1 predicated STS
        buf ^= 1;                           // double-buffer: next step uses other slots
    }
    __syncthreads();  // s_idx complete

    // Batched writeout of indices + selected points (off the critical loop).
    for (int r = tid; r < MSEL; r += NTHREADS) {
        int id = s_idx[r];
        g_sel_idx[b * MSEL + r] = id;
        size_t o = ((size_t)b * MSEL + r) * 3;
        dp_out[o + 0] = s_pos2[6 * id + 0];
        dp_out[o + 1] = s_pos2[6 * id + 2];
        dp_out[o + 2] = s_pos2[6 * id + 4];
    }
}

// ---------------- Feature gather: [B, m, 256] float32 ----------------
__global__ void gather_kernel(const float* __restrict__ feat, float* __restrict__ df_out)
{
    // 256 threads/block -> 4 rows/block, 64 threads (float4 x 64 = 256 floats) per row.
    int r = blockIdx.x * 4 + (threadIdx.x >> 6);
    int c = threadIdx.x & 63;
    int b = r >> 12;  // r / 4096
    int id = g_sel_idx[r];
    const float4* src = (const float4*)(feat + ((size_t)b * NPTS + id) * 256);
    float4 v = src[c];
    ((float4*)df_out)[(size_t)r * 64 + c] = v;
}

extern "C" void kernel_launch(void* const* d_in, const int* in_sizes, int n_in,
                              void* d_out, int out_size)
{
    (void)n_in; (void)out_size;
    const float* points;
    const float* feats;
    if (in_sizes[0] == BATCH * NPTS * 3) {
        points = (const float*)d_in[0];
        feats  = (const float*)d_in[1];
    } else {
        points = (const float*)d_in[1];
        feats  = (const float*)d_in[0];
    }

    float* out = (float*)d_out;
    float* dp  = out;                              // [B, m, 3]
    float* df  = out + (size_t)BATCH * MSEL * 3;   // [B, m, 256]

    cudaFuncSetAttribute(fps_kernel, cudaFuncAttributeMaxDynamicSharedMemorySize,
                         SMEM_BYTES);
    fps_kernel<<<BATCH, NTHREADS, SMEM_BYTES>>>(points, dp);
    gather_kernel<<<(BATCH * MSEL) / 4, 256>>>(feats, df);
}